// round 6
// baseline (speedup 1.0000x reference)
#include <cuda_runtime.h>
#include <math.h>

// S=4, B=4, T=4096, D=1024 (fixed per reference setup_inputs)
#define S_STREAMS 4
#define T_LEN 4096
#define D_DIM 1024
#define DV (D_DIM / 4)          // 256 float4 per row
#define SINKHORN_ITERS 20
#define EPS 1e-5f

// scratch for tiny precomputed scalars: [0..3]=h_pre, [4..7]=c
__device__ float g_hc_params[8];

// Fast-math precompute (~1.3k serial cycles).
__global__ void hc_precompute_kernel(const float* __restrict__ H_pre_logits,
                                     const float* __restrict__ H_post_logits,
                                     const float* __restrict__ H_res) {
    if (threadIdx.x != 0) return;
    float M[4][4];
    #pragma unroll
    for (int i = 0; i < 4; i++)
        #pragma unroll
        for (int j = 0; j < 4; j++)
            M[i][j] = __expf(H_res[i * 4 + j]);

    #pragma unroll 4
    for (int it = 0; it < SINKHORN_ITERS; it++) {
        #pragma unroll
        for (int i = 0; i < 4; i++) {
            float s = (M[i][0] + M[i][1]) + (M[i][2] + M[i][3]) + EPS;
            float inv = __fdividef(1.0f, s);
            #pragma unroll
            for (int j = 0; j < 4; j++) M[i][j] *= inv;
        }
        #pragma unroll
        for (int j = 0; j < 4; j++) {
            float s = (M[0][j] + M[1][j]) + (M[2][j] + M[3][j]) + EPS;
            float inv = __fdividef(1.0f, s);
            #pragma unroll
            for (int i = 0; i < 4; i++) M[i][j] *= inv;
        }
    }

    float h_post[4];
    #pragma unroll
    for (int r = 0; r < 4; r++)
        h_post[r] = 2.0f * __fdividef(1.0f, 1.0f + __expf(-H_post_logits[r]));

    #pragma unroll
    for (int s = 0; s < 4; s++) {
        g_hc_params[s] = __fdividef(1.0f, 1.0f + __expf(-H_pre_logits[s]));
        float c = 0.0f;
        #pragma unroll
        for (int r = 0; r < 4; r++) c += M[s][r] * h_post[r];
        g_hc_params[4 + s] = c;
    }
}

// One WARP per token: no __syncthreads, no shared memory, no inter-warp
// coupling. Phase 1 streams the token's 4x1024 floats (default caching so
// lines stay hot in L1/L2), warp-shuffle RMS reduce, phase 2 re-reads the
// (cached) lines, recomputes the aggregate, and writes with evict-first.
__global__ __launch_bounds__(256, 4)
void hc_main_kernel(const float4* __restrict__ x,
                    const float4* __restrict__ w,
                    float4* __restrict__ out) {
    const int wid  = threadIdx.x >> 5;
    const int lane = threadIdx.x & 31;
    const int n    = blockIdx.x * 8 + wid;   // token id, 0 .. 16383
    const int b    = n >> 12;                // / T_LEN
    const int t    = n & (T_LEN - 1);

    const long strideS = (long)T_LEN * DV;
    const long base    = (long)(b * 4) * strideS + (long)t * DV + lane;

    const float hp0 = g_hc_params[0], hp1 = g_hc_params[1];
    const float hp2 = g_hc_params[2], hp3 = g_hc_params[3];
    const float c0  = g_hc_params[4], c1  = g_hc_params[5];
    const float c2  = g_hc_params[6], c3  = g_hc_params[7];

    // ---- phase 1: accumulate sum of squares of the aggregate ----
    float ss = 0.0f;
    #pragma unroll 4
    for (int j = 0; j < 8; j++) {
        const long idx = base + j * 32;
        const float4 x0 = x[idx];
        const float4 x1 = x[idx + strideS];
        const float4 x2 = x[idx + 2 * strideS];
        const float4 x3 = x[idx + 3 * strideS];
        float4 a;
        a.x = hp0 * x0.x + hp1 * x1.x + hp2 * x2.x + hp3 * x3.x;
        a.y = hp0 * x0.y + hp1 * x1.y + hp2 * x2.y + hp3 * x3.y;
        a.z = hp0 * x0.z + hp1 * x1.z + hp2 * x2.z + hp3 * x3.z;
        a.w = hp0 * x0.w + hp1 * x1.w + hp2 * x2.w + hp3 * x3.w;
        ss += a.x * a.x + a.y * a.y + a.z * a.z + a.w * a.w;
    }

    // warp-only reduction (token fully owned by this warp)
    #pragma unroll
    for (int off = 16; off > 0; off >>= 1)
        ss += __shfl_xor_sync(0xFFFFFFFFu, ss, off);
    const float inv_rms = rsqrtf(ss * (1.0f / (float)D_DIM) + EPS);

    // ---- phase 2: re-read (L1/L2 hot), recompute aggregate, write out ----
    #pragma unroll 4
    for (int j = 0; j < 8; j++) {
        const long idx = base + j * 32;
        const float4 x0 = __ldcs(x + idx);
        const float4 x1 = __ldcs(x + idx + strideS);
        const float4 x2 = __ldcs(x + idx + 2 * strideS);
        const float4 x3 = __ldcs(x + idx + 3 * strideS);
        const float4 wv = w[lane + j * 32];

        float4 a;
        a.x = hp0 * x0.x + hp1 * x1.x + hp2 * x2.x + hp3 * x3.x;
        a.y = hp0 * x0.y + hp1 * x1.y + hp2 * x2.y + hp3 * x3.y;
        a.z = hp0 * x0.z + hp1 * x1.z + hp2 * x2.z + hp3 * x3.z;
        a.w = hp0 * x0.w + hp1 * x1.w + hp2 * x2.w + hp3 * x3.w;

        float4 xn;
        xn.x = a.x * inv_rms * wv.x;
        xn.y = a.y * inv_rms * wv.y;
        xn.z = a.z * inv_rms * wv.z;
        xn.w = a.w * inv_rms * wv.w;

        float4 o;
        o.x = x0.x + c0 * xn.x; o.y = x0.y + c0 * xn.y;
        o.z = x0.z + c0 * xn.z; o.w = x0.w + c0 * xn.w;
        __stcs(out + idx, o);
        o.x = x1.x + c1 * xn.x; o.y = x1.y + c1 * xn.y;
        o.z = x1.z + c1 * xn.z; o.w = x1.w + c1 * xn.w;
        __stcs(out + idx + strideS, o);
        o.x = x2.x + c2 * xn.x; o.y = x2.y + c2 * xn.y;
        o.z = x2.z + c2 * xn.z; o.w = x2.w + c2 * xn.w;
        __stcs(out + idx + 2 * strideS, o);
        o.x = x3.x + c3 * xn.x; o.y = x3.y + c3 * xn.y;
        o.z = x3.z + c3 * xn.z; o.w = x3.w + c3 * xn.w;
        __stcs(out + idx + 3 * strideS, o);
    }
}

extern "C" void kernel_launch(void* const* d_in, const int* in_sizes, int n_in,
                              void* d_out, int out_size) {
    const float* residuals      = (const float*)d_in[0];  // (B*S, T, D) fp32
    const float* rmsnorm_weight = (const float*)d_in[1];  // (D,)
    const float* H_pre_logits   = (const float*)d_in[2];  // (S,)
    const float* H_post_logits  = (const float*)d_in[3];  // (S,)
    const float* H_res          = (const float*)d_in[4];  // (S, S)
    float* out = (float*)d_out;

    const int BS = in_sizes[0] / (T_LEN * D_DIM);  // B*S = 16
    const int B  = BS / S_STREAMS;                 // 4
    const int n_tokens = B * T_LEN;                // 16384
    const int n_blocks = n_tokens / 8;             // 2048 (8 warps = 8 tokens/block)

    hc_precompute_kernel<<<1, 32>>>(H_pre_logits, H_post_logits, H_res);
    hc_main_kernel<<<n_blocks, 256>>>((const float4*)residuals,
                                      (const float4*)rmsnorm_weight,
                                      (float4*)out);
}

// round 7
// speedup vs baseline: 1.1657x; 1.1657x over previous
#include <cuda_runtime.h>
#include <math.h>

// S=4, B=4, T=4096, D=1024 (fixed per reference setup_inputs)
#define S_STREAMS 4
#define T_LEN 4096
#define D_DIM 1024
#define DV (D_DIM / 4)          // 256 float4 per row
#define SINKHORN_ITERS 20
#define EPS 1e-5f

// precomputed scalars: [0..3]=h_pre, [4..7]=c
__device__ float g_hc_params[8];

// Primary kernel (PDL): trigger launch of the dependent kernel IMMEDIATELY,
// then do the ~1.3k-cycle serial fast-math precompute. The secondary's
// cudaGridDependencySynchronize() guarantees visibility of our writes.
__global__ void hc_precompute_kernel(const float* __restrict__ H_pre_logits,
                                     const float* __restrict__ H_post_logits,
                                     const float* __restrict__ H_res) {
    cudaTriggerProgrammaticLaunchCompletion();

    float M[4][4];
    #pragma unroll
    for (int i = 0; i < 4; i++)
        #pragma unroll
        for (int j = 0; j < 4; j++)
            M[i][j] = __expf(H_res[i * 4 + j]);

    #pragma unroll 4
    for (int it = 0; it < SINKHORN_ITERS; it++) {
        #pragma unroll
        for (int i = 0; i < 4; i++) {
            float s = (M[i][0] + M[i][1]) + (M[i][2] + M[i][3]) + EPS;
            float inv = __fdividef(1.0f, s);
            #pragma unroll
            for (int j = 0; j < 4; j++) M[i][j] *= inv;
        }
        #pragma unroll
        for (int j = 0; j < 4; j++) {
            float s = (M[0][j] + M[1][j]) + (M[2][j] + M[3][j]) + EPS;
            float inv = __fdividef(1.0f, s);
            #pragma unroll
            for (int i = 0; i < 4; i++) M[i][j] *= inv;
        }
    }

    float h_post[4];
    #pragma unroll
    for (int r = 0; r < 4; r++)
        h_post[r] = 2.0f * __fdividef(1.0f, 1.0f + __expf(-H_post_logits[r]));

    #pragma unroll
    for (int s = 0; s < 4; s++) {
        g_hc_params[s] = __fdividef(1.0f, 1.0f + __expf(-H_pre_logits[s]));
        float c = 0.0f;
        #pragma unroll
        for (int r = 0; r < 4; r++) c += M[s][r] * h_post[r];
        g_hc_params[4 + s] = c;
    }
}

// Secondary kernel (PDL): one block per token. Issues its 4 independent
// x LDG.128s (param-independent) BEFORE blocking on the grid dependency,
// so the precompute hides under first-wave DRAM latency.
__global__ __launch_bounds__(256, 8)
void hc_main_kernel(const float4* __restrict__ x,
                    const float4* __restrict__ w,
                    float4* __restrict__ out) {
    const int n   = blockIdx.x;          // 0 .. B*T-1
    const int b   = n >> 12;             // / 4096
    const int t   = n & (T_LEN - 1);
    const int tid = threadIdx.x;

    const long strideS = (long)T_LEN * DV;
    const long base    = (long)(b * 4) * strideS + (long)t * DV + tid;

    // param-independent loads first (overlap with primary kernel)
    const float4 x0 = x[base];
    const float4 x1 = x[base + strideS];
    const float4 x2 = x[base + 2 * strideS];
    const float4 x3 = x[base + 3 * strideS];
    const float4 wv = w[tid];

    // wait until precompute's writes to g_hc_params are visible
    cudaGridDependencySynchronize();

    const float hp0 = g_hc_params[0], hp1 = g_hc_params[1];
    const float hp2 = g_hc_params[2], hp3 = g_hc_params[3];
    const float c0  = g_hc_params[4], c1  = g_hc_params[5];
    const float c2  = g_hc_params[6], c3  = g_hc_params[7];

    float4 a;
    a.x = hp0 * x0.x + hp1 * x1.x + hp2 * x2.x + hp3 * x3.x;
    a.y = hp0 * x0.y + hp1 * x1.y + hp2 * x2.y + hp3 * x3.y;
    a.z = hp0 * x0.z + hp1 * x1.z + hp2 * x2.z + hp3 * x3.z;
    a.w = hp0 * x0.w + hp1 * x1.w + hp2 * x2.w + hp3 * x3.w;

    float ss = a.x * a.x + a.y * a.y + a.z * a.z + a.w * a.w;

    __shared__ float warp_sums[8];
    #pragma unroll
    for (int off = 16; off > 0; off >>= 1)
        ss += __shfl_xor_sync(0xFFFFFFFFu, ss, off);
    if ((tid & 31) == 0) warp_sums[tid >> 5] = ss;
    __syncthreads();     // single barrier

    const float tot = (warp_sums[0] + warp_sums[1]) + (warp_sums[2] + warp_sums[3])
                    + (warp_sums[4] + warp_sums[5]) + (warp_sums[6] + warp_sums[7]);
    const float inv_rms = rsqrtf(tot * (1.0f / (float)D_DIM) + EPS);

    float4 xn;
    xn.x = a.x * inv_rms * wv.x;
    xn.y = a.y * inv_rms * wv.y;
    xn.z = a.z * inv_rms * wv.z;
    xn.w = a.w * inv_rms * wv.w;

    float4 o;
    o.x = x0.x + c0 * xn.x; o.y = x0.y + c0 * xn.y;
    o.z = x0.z + c0 * xn.z; o.w = x0.w + c0 * xn.w;
    out[base] = o;
    o.x = x1.x + c1 * xn.x; o.y = x1.y + c1 * xn.y;
    o.z = x1.z + c1 * xn.z; o.w = x1.w + c1 * xn.w;
    out[base + strideS] = o;
    o.x = x2.x + c2 * xn.x; o.y = x2.y + c2 * xn.y;
    o.z = x2.z + c2 * xn.z; o.w = x2.w + c2 * xn.w;
    out[base + 2 * strideS] = o;
    o.x = x3.x + c3 * xn.x; o.y = x3.y + c3 * xn.y;
    o.z = x3.z + c3 * xn.z; o.w = x3.w + c3 * xn.w;
    out[base + 3 * strideS] = o;
}

extern "C" void kernel_launch(void* const* d_in, const int* in_sizes, int n_in,
                              void* d_out, int out_size) {
    const float* residuals      = (const float*)d_in[0];  // (B*S, T, D) fp32
    const float* rmsnorm_weight = (const float*)d_in[1];  // (D,)
    const float* H_pre_logits   = (const float*)d_in[2];  // (S,)
    const float* H_post_logits  = (const float*)d_in[3];  // (S,)
    const float* H_res          = (const float*)d_in[4];  // (S, S)
    float* out = (float*)d_out;

    const int BS = in_sizes[0] / (T_LEN * D_DIM);  // B*S = 16
    const int B  = BS / S_STREAMS;                 // 4
    const int n_tokens = B * T_LEN;                // 16384

    hc_precompute_kernel<<<1, 1>>>(H_pre_logits, H_post_logits, H_res);

    // dependent launch: overlap main-kernel launch + param-independent loads
    // with the precompute kernel
    cudaLaunchConfig_t cfg = {};
    cfg.gridDim  = dim3(n_tokens, 1, 1);
    cfg.blockDim = dim3(256, 1, 1);
    cfg.dynamicSmemBytes = 0;
    cfg.stream = 0;
    cudaLaunchAttribute attrs[1];
    attrs[0].id = cudaLaunchAttributeProgrammaticStreamSerialization;
    attrs[0].val.programmaticStreamSerializationAllowed = 1;
    cfg.attrs = attrs;
    cfg.numAttrs = 1;

    cudaLaunchKernelEx(&cfg, hc_main_kernel,
                       (const float4*)residuals,
                       (const float4*)rmsnorm_weight,
                       (float4*)out);
}

// round 8
// speedup vs baseline: 1.1945x; 1.0246x over previous
#include <cuda_runtime.h>
#include <math.h>

// S=4, B=4, T=4096, D=1024 (fixed per reference setup_inputs)
#define S_STREAMS 4
#define T_LEN 4096
#define D_DIM 1024
#define DV (D_DIM / 4)          // 256 float4 per row
#define SINKHORN_ITERS 20
#define EPS 1e-5f

// precomputed scalars: [0..3]=h_pre, [4..7]=c
__device__ float g_hc_params[8];

// Primary kernel (PDL): trigger the dependent launch IMMEDIATELY, then do the
// ~1.3k-cycle serial fast-math precompute. The secondary's
// cudaGridDependencySynchronize() guarantees visibility of these writes.
__global__ void hc_precompute_kernel(const float* __restrict__ H_pre_logits,
                                     const float* __restrict__ H_post_logits,
                                     const float* __restrict__ H_res) {
    cudaTriggerProgrammaticLaunchCompletion();

    float M[4][4];
    #pragma unroll
    for (int i = 0; i < 4; i++)
        #pragma unroll
        for (int j = 0; j < 4; j++)
            M[i][j] = __expf(H_res[i * 4 + j]);

    #pragma unroll 4
    for (int it = 0; it < SINKHORN_ITERS; it++) {
        #pragma unroll
        for (int i = 0; i < 4; i++) {
            float s = (M[i][0] + M[i][1]) + (M[i][2] + M[i][3]) + EPS;
            float inv = __fdividef(1.0f, s);
            #pragma unroll
            for (int j = 0; j < 4; j++) M[i][j] *= inv;
        }
        #pragma unroll
        for (int j = 0; j < 4; j++) {
            float s = (M[0][j] + M[1][j]) + (M[2][j] + M[3][j]) + EPS;
            float inv = __fdividef(1.0f, s);
            #pragma unroll
            for (int i = 0; i < 4; i++) M[i][j] *= inv;
        }
    }

    float h_post[4];
    #pragma unroll
    for (int r = 0; r < 4; r++)
        h_post[r] = 2.0f * __fdividef(1.0f, 1.0f + __expf(-H_post_logits[r]));

    #pragma unroll
    for (int s = 0; s < 4; s++) {
        g_hc_params[s] = __fdividef(1.0f, 1.0f + __expf(-H_pre_logits[s]));
        float c = 0.0f;
        #pragma unroll
        for (int r = 0; r < 4; r++) c += M[s][r] * h_post[r];
        g_hc_params[4 + s] = c;
    }
}

// Secondary kernel (PDL): one block per token, R5's proven body.
// Param-independent streaming loads are issued BEFORE the grid-dependency
// wait so they overlap the precompute kernel. Evict-first on both the
// x reads and out writes (each line touched exactly once).
__global__ __launch_bounds__(256, 8)
void hc_main_kernel(const float4* __restrict__ x,
                    const float4* __restrict__ w,
                    float4* __restrict__ out) {
    const int n   = blockIdx.x;          // 0 .. B*T-1
    const int b   = n >> 12;             // / 4096
    const int t   = n & (T_LEN - 1);
    const int tid = threadIdx.x;

    const long strideS = (long)T_LEN * DV;
    const long base    = (long)(b * 4) * strideS + (long)t * DV + tid;

    // param-independent streaming loads first (overlap with primary kernel)
    const float4 x0 = __ldcs(x + base);
    const float4 x1 = __ldcs(x + base + strideS);
    const float4 x2 = __ldcs(x + base + 2 * strideS);
    const float4 x3 = __ldcs(x + base + 3 * strideS);
    const float4 wv = w[tid];

    // wait until precompute's writes to g_hc_params are visible
    cudaGridDependencySynchronize();

    const float hp0 = g_hc_params[0], hp1 = g_hc_params[1];
    const float hp2 = g_hc_params[2], hp3 = g_hc_params[3];
    const float c0  = g_hc_params[4], c1  = g_hc_params[5];
    const float c2  = g_hc_params[6], c3  = g_hc_params[7];

    float4 a;
    a.x = hp0 * x0.x + hp1 * x1.x + hp2 * x2.x + hp3 * x3.x;
    a.y = hp0 * x0.y + hp1 * x1.y + hp2 * x2.y + hp3 * x3.y;
    a.z = hp0 * x0.z + hp1 * x1.z + hp2 * x2.z + hp3 * x3.z;
    a.w = hp0 * x0.w + hp1 * x1.w + hp2 * x2.w + hp3 * x3.w;

    float ss = a.x * a.x + a.y * a.y + a.z * a.z + a.w * a.w;

    __shared__ float warp_sums[8];
    #pragma unroll
    for (int off = 16; off > 0; off >>= 1)
        ss += __shfl_xor_sync(0xFFFFFFFFu, ss, off);
    if ((tid & 31) == 0) warp_sums[tid >> 5] = ss;
    __syncthreads();     // single barrier

    const float tot = (warp_sums[0] + warp_sums[1]) + (warp_sums[2] + warp_sums[3])
                    + (warp_sums[4] + warp_sums[5]) + (warp_sums[6] + warp_sums[7]);
    const float inv_rms = rsqrtf(tot * (1.0f / (float)D_DIM) + EPS);

    float4 xn;
    xn.x = a.x * inv_rms * wv.x;
    xn.y = a.y * inv_rms * wv.y;
    xn.z = a.z * inv_rms * wv.z;
    xn.w = a.w * inv_rms * wv.w;

    float4 o;
    o.x = x0.x + c0 * xn.x; o.y = x0.y + c0 * xn.y;
    o.z = x0.z + c0 * xn.z; o.w = x0.w + c0 * xn.w;
    __stcs(out + base, o);
    o.x = x1.x + c1 * xn.x; o.y = x1.y + c1 * xn.y;
    o.z = x1.z + c1 * xn.z; o.w = x1.w + c1 * xn.w;
    __stcs(out + base + strideS, o);
    o.x = x2.x + c2 * xn.x; o.y = x2.y + c2 * xn.y;
    o.z = x2.z + c2 * xn.z; o.w = x2.w + c2 * xn.w;
    __stcs(out + base + 2 * strideS, o);
    o.x = x3.x + c3 * xn.x; o.y = x3.y + c3 * xn.y;
    o.z = x3.z + c3 * xn.z; o.w = x3.w + c3 * xn.w;
    __stcs(out + base + 3 * strideS, o);
}

extern "C" void kernel_launch(void* const* d_in, const int* in_sizes, int n_in,
                              void* d_out, int out_size) {
    const float* residuals      = (const float*)d_in[0];  // (B*S, T, D) fp32
    const float* rmsnorm_weight = (const float*)d_in[1];  // (D,)
    const float* H_pre_logits   = (const float*)d_in[2];  // (S,)
    const float* H_post_logits  = (const float*)d_in[3];  // (S,)
    const float* H_res          = (const float*)d_in[4];  // (S, S)
    float* out = (float*)d_out;

    const int BS = in_sizes[0] / (T_LEN * D_DIM);  // B*S = 16
    const int B  = BS / S_STREAMS;                 // 4
    const int n_tokens = B * T_LEN;                // 16384

    hc_precompute_kernel<<<1, 1>>>(H_pre_logits, H_post_logits, H_res);

    // dependent launch: overlap main-kernel launch + param-independent loads
    // with the precompute kernel
    cudaLaunchConfig_t cfg = {};
    cfg.gridDim  = dim3(n_tokens, 1, 1);
    cfg.blockDim = dim3(256, 1, 1);
    cfg.dynamicSmemBytes = 0;
    cfg.stream = 0;
    cudaLaunchAttribute attrs[1];
    attrs[0].id = cudaLaunchAttributeProgrammaticStreamSerialization;
    attrs[0].val.programmaticStreamSerializationAllowed = 1;
    cfg.attrs = attrs;
    cfg.numAttrs = 1;

    cudaLaunchKernelEx(&cfg, hc_main_kernel,
                       (const float4*)residuals,
                       (const float4*)rmsnorm_weight,
                       (float4*)out);
}

// round 9
// speedup vs baseline: 1.2218x; 1.0229x over previous
#include <cuda_runtime.h>
#include <math.h>

// S=4, B=4, T=4096, D=1024 (fixed per reference setup_inputs)
#define S_STREAMS 4
#define T_LEN 4096
#define D_DIM 1024
#define DV (D_DIM / 4)          // 256 float4 per row
#define SINKHORN_ITERS 20
#define EPS 1e-5f

// precomputed scalars: [0..3]=h_pre, [4..7]=c
__device__ float g_hc_params[8];

// Primary kernel (PDL): trigger the dependent launch IMMEDIATELY, then do the
// ~1.3k-cycle serial fast-math precompute.
__global__ void hc_precompute_kernel(const float* __restrict__ H_pre_logits,
                                     const float* __restrict__ H_post_logits,
                                     const float* __restrict__ H_res) {
    cudaTriggerProgrammaticLaunchCompletion();

    float M[4][4];
    #pragma unroll
    for (int i = 0; i < 4; i++)
        #pragma unroll
        for (int j = 0; j < 4; j++)
            M[i][j] = __expf(H_res[i * 4 + j]);

    #pragma unroll 4
    for (int it = 0; it < SINKHORN_ITERS; it++) {
        #pragma unroll
        for (int i = 0; i < 4; i++) {
            float s = (M[i][0] + M[i][1]) + (M[i][2] + M[i][3]) + EPS;
            float inv = __fdividef(1.0f, s);
            #pragma unroll
            for (int j = 0; j < 4; j++) M[i][j] *= inv;
        }
        #pragma unroll
        for (int j = 0; j < 4; j++) {
            float s = (M[0][j] + M[1][j]) + (M[2][j] + M[3][j]) + EPS;
            float inv = __fdividef(1.0f, s);
            #pragma unroll
            for (int i = 0; i < 4; i++) M[i][j] *= inv;
        }
    }

    float h_post[4];
    #pragma unroll
    for (int r = 0; r < 4; r++)
        h_post[r] = 2.0f * __fdividef(1.0f, 1.0f + __expf(-H_post_logits[r]));

    #pragma unroll
    for (int s = 0; s < 4; s++) {
        g_hc_params[s] = __fdividef(1.0f, 1.0f + __expf(-H_pre_logits[s]));
        float c = 0.0f;
        #pragma unroll
        for (int r = 0; r < 4; r++) c += M[s][r] * h_post[r];
        g_hc_params[4 + s] = c;
    }
}

// Secondary kernel (PDL): one 128-thread block per token; each thread owns
// float4 chunks tid and tid+128 -> 8 independent front-batched LDG.128
// (MLP_p1=8, 4KB/warp in flight) and a 4-warp reduction barrier.
__global__ __launch_bounds__(128, 8)
void hc_main_kernel(const float4* __restrict__ x,
                    const float4* __restrict__ w,
                    float4* __restrict__ out) {
    const int n   = blockIdx.x;          // 0 .. B*T-1
    const int b   = n >> 12;             // / 4096
    const int t   = n & (T_LEN - 1);
    const int tid = threadIdx.x;         // 0..127

    const long strideS = (long)T_LEN * DV;
    const long baseA   = (long)(b * 4) * strideS + (long)t * DV + tid;
    const long baseB   = baseA + 128;

    // param-independent streaming loads FIRST: 8 independent LDG.128
    // (overlaps the precompute kernel via PDL)
    const float4 xa0 = __ldcs(x + baseA);
    const float4 xa1 = __ldcs(x + baseA + strideS);
    const float4 xa2 = __ldcs(x + baseA + 2 * strideS);
    const float4 xa3 = __ldcs(x + baseA + 3 * strideS);
    const float4 xb0 = __ldcs(x + baseB);
    const float4 xb1 = __ldcs(x + baseB + strideS);
    const float4 xb2 = __ldcs(x + baseB + 2 * strideS);
    const float4 xb3 = __ldcs(x + baseB + 3 * strideS);
    const float4 wa  = w[tid];
    const float4 wb  = w[tid + 128];

    cudaGridDependencySynchronize();

    const float hp0 = g_hc_params[0], hp1 = g_hc_params[1];
    const float hp2 = g_hc_params[2], hp3 = g_hc_params[3];
    const float c0  = g_hc_params[4], c1  = g_hc_params[5];
    const float c2  = g_hc_params[6], c3  = g_hc_params[7];

    float4 aA, aB;
    aA.x = hp0 * xa0.x + hp1 * xa1.x + hp2 * xa2.x + hp3 * xa3.x;
    aA.y = hp0 * xa0.y + hp1 * xa1.y + hp2 * xa2.y + hp3 * xa3.y;
    aA.z = hp0 * xa0.z + hp1 * xa1.z + hp2 * xa2.z + hp3 * xa3.z;
    aA.w = hp0 * xa0.w + hp1 * xa1.w + hp2 * xa2.w + hp3 * xa3.w;
    aB.x = hp0 * xb0.x + hp1 * xb1.x + hp2 * xb2.x + hp3 * xb3.x;
    aB.y = hp0 * xb0.y + hp1 * xb1.y + hp2 * xb2.y + hp3 * xb3.y;
    aB.z = hp0 * xb0.z + hp1 * xb1.z + hp2 * xb2.z + hp3 * xb3.z;
    aB.w = hp0 * xb0.w + hp1 * xb1.w + hp2 * xb2.w + hp3 * xb3.w;

    float ss = aA.x * aA.x + aA.y * aA.y + aA.z * aA.z + aA.w * aA.w
             + aB.x * aB.x + aB.y * aB.y + aB.z * aB.z + aB.w * aB.w;

    __shared__ float warp_sums[4];
    #pragma unroll
    for (int off = 16; off > 0; off >>= 1)
        ss += __shfl_xor_sync(0xFFFFFFFFu, ss, off);
    if ((tid & 31) == 0) warp_sums[tid >> 5] = ss;
    __syncthreads();     // single barrier, 4 warps

    const float tot = (warp_sums[0] + warp_sums[1]) + (warp_sums[2] + warp_sums[3]);
    const float inv_rms = rsqrtf(tot * (1.0f / (float)D_DIM) + EPS);

    float4 xnA, xnB;
    xnA.x = aA.x * inv_rms * wa.x;
    xnA.y = aA.y * inv_rms * wa.y;
    xnA.z = aA.z * inv_rms * wa.z;
    xnA.w = aA.w * inv_rms * wa.w;
    xnB.x = aB.x * inv_rms * wb.x;
    xnB.y = aB.y * inv_rms * wb.y;
    xnB.z = aB.z * inv_rms * wb.z;
    xnB.w = aB.w * inv_rms * wb.w;

    float4 o;
    o.x = xa0.x + c0 * xnA.x; o.y = xa0.y + c0 * xnA.y;
    o.z = xa0.z + c0 * xnA.z; o.w = xa0.w + c0 * xnA.w;
    __stcs(out + baseA, o);
    o.x = xb0.x + c0 * xnB.x; o.y = xb0.y + c0 * xnB.y;
    o.z = xb0.z + c0 * xnB.z; o.w = xb0.w + c0 * xnB.w;
    __stcs(out + baseB, o);

    o.x = xa1.x + c1 * xnA.x; o.y = xa1.y + c1 * xnA.y;
    o.z = xa1.z + c1 * xnA.z; o.w = xa1.w + c1 * xnA.w;
    __stcs(out + baseA + strideS, o);
    o.x = xb1.x + c1 * xnB.x; o.y = xb1.y + c1 * xnB.y;
    o.z = xb1.z + c1 * xnB.z; o.w = xb1.w + c1 * xnB.w;
    __stcs(out + baseB + strideS, o);

    o.x = xa2.x + c2 * xnA.x; o.y = xa2.y + c2 * xnA.y;
    o.z = xa2.z + c2 * xnA.z; o.w = xa2.w + c2 * xnA.w;
    __stcs(out + baseA + 2 * strideS, o);
    o.x = xb2.x + c2 * xnB.x; o.y = xb2.y + c2 * xnB.y;
    o.z = xb2.z + c2 * xnB.z; o.w = xb2.w + c2 * xnB.w;
    __stcs(out + baseB + 2 * strideS, o);

    o.x = xa3.x + c3 * xnA.x; o.y = xa3.y + c3 * xnA.y;
    o.z = xa3.z + c3 * xnA.z; o.w = xa3.w + c3 * xnA.w;
    __stcs(out + baseA + 3 * strideS, o);
    o.x = xb3.x + c3 * xnB.x; o.y = xb3.y + c3 * xnB.y;
    o.z = xb3.z + c3 * xnB.z; o.w = xb3.w + c3 * xnB.w;
    __stcs(out + baseB + 3 * strideS, o);
}

extern "C" void kernel_launch(void* const* d_in, const int* in_sizes, int n_in,
                              void* d_out, int out_size) {
    const float* residuals      = (const float*)d_in[0];  // (B*S, T, D) fp32
    const float* rmsnorm_weight = (const float*)d_in[1];  // (D,)
    const float* H_pre_logits   = (const float*)d_in[2];  // (S,)
    const float* H_post_logits  = (const float*)d_in[3];  // (S,)
    const float* H_res          = (const float*)d_in[4];  // (S, S)
    float* out = (float*)d_out;

    const int BS = in_sizes[0] / (T_LEN * D_DIM);  // B*S = 16
    const int B  = BS / S_STREAMS;                 // 4
    const int n_tokens = B * T_LEN;                // 16384

    hc_precompute_kernel<<<1, 1>>>(H_pre_logits, H_post_logits, H_res);

    cudaLaunchConfig_t cfg = {};
    cfg.gridDim  = dim3(n_tokens, 1, 1);
    cfg.blockDim = dim3(128, 1, 1);
    cfg.dynamicSmemBytes = 0;
    cfg.stream = 0;
    cudaLaunchAttribute attrs[1];
    attrs[0].id = cudaLaunchAttributeProgrammaticStreamSerialization;
    attrs[0].val.programmaticStreamSerializationAllowed = 1;
    cfg.attrs = attrs;
    cfg.numAttrs = 1;

    cudaLaunchKernelEx(&cfg, hc_main_kernel,
                       (const float4*)residuals,
                       (const float4*)rmsnorm_weight,
                       (float4*)out);
}